// round 7
// baseline (speedup 1.0000x reference)
#include <cuda_runtime.h>
#include <cuda_fp16.h>
#include <cstdint>

#define N_OUT 4096
#define M_IN  4096
#define BATCH 128
#define KTOT  4096
#define BN    64
#define SPLITK 4
#define KPER  (KTOT / SPLITK)   // 1024
#define BK    64
#define KT    (KPER / BK)       // 16
#define ASTAGES 4
#define NNZ_MAX 1638400

// smem layout (dynamic): [0,131072) = B 64x1024 fp16 (16 k-tiles of 8KB),
// [131072, 131072+4*16384) = A stages. Total 192KB.
#define SMEM_B_BYTES (BN * KPER * 2)            // 131072
#define SMEM_A_OFF   SMEM_B_BYTES
#define ASTG_BYTES   (BATCH * BK * 2)           // 16384
#define SMEM_BYTES   (SMEM_B_BYTES + ASTAGES * ASTG_BYTES)  // 196608

// Device scratch (no allocation allowed)
__device__ __align__(16) __half   g_xh[BATCH * M_IN];   // x in fp16 (1MB)
__device__ __align__(16) uint32_t g_pk[NNZ_MAX];        // packed (row,col,val) (6.4MB)
__device__ int g_grp[65];                               // 64-row group boundaries

// ---------------------------------------------------------------------------
__device__ __forceinline__ uint32_t smem_u32(const void* p) {
    return (uint32_t)__cvta_generic_to_shared(p);
}
__device__ __forceinline__ void cpasync16(uint32_t dst, const void* src) {
    asm volatile("cp.async.cg.shared.global [%0], [%1], 16;" :: "r"(dst), "l"(src));
}
__device__ __forceinline__ void ldsm4(uint32_t* r, uint32_t a) {
    asm volatile("ldmatrix.sync.aligned.m8n8.x4.shared.b16 {%0,%1,%2,%3}, [%4];"
                 : "=r"(r[0]), "=r"(r[1]), "=r"(r[2]), "=r"(r[3]) : "r"(a));
}
__device__ __forceinline__ void ldsm2(uint32_t* r, uint32_t a) {
    asm volatile("ldmatrix.sync.aligned.m8n8.x2.shared.b16 {%0,%1}, [%2];"
                 : "=r"(r[0]), "=r"(r[1]) : "r"(a));
}
__device__ __forceinline__ void mma16816(float* c, const uint32_t* a, const uint32_t* b) {
    asm volatile(
        "mma.sync.aligned.m16n8k16.row.col.f32.f16.f16.f32 "
        "{%0,%1,%2,%3}, {%4,%5,%6,%7}, {%8,%9}, {%0,%1,%2,%3};"
        : "+f"(c[0]), "+f"(c[1]), "+f"(c[2]), "+f"(c[3])
        : "r"(a[0]), "r"(a[1]), "r"(a[2]), "r"(a[3]), "r"(b[0]), "r"(b[1]));
}
__device__ __forceinline__ void redv2(float* p, float x, float y) {
    asm volatile("red.global.add.v2.f32 [%0], {%1, %2};"
                 :: "l"(p), "f"(x), "f"(y) : "memory");
}

// ---------------------------------------------------------------------------
// K0: x -> fp16, out = bias, pack nnz, group boundaries
// ---------------------------------------------------------------------------
__global__ void k_prep(const float* __restrict__ x,
                       const float* __restrict__ bias,
                       float* __restrict__ out,
                       const int* __restrict__ val,
                       const int* __restrict__ rows,
                       const int* __restrict__ cols,
                       int nnz) {
    const int gid = blockIdx.x * blockDim.x + threadIdx.x;

    if (gid < nnz) {
        int r = rows[gid];
        uint32_t pk = ((uint32_t)r << 20) | (((uint32_t)cols[gid] & 0xFFF) << 8)
                    | ((uint32_t)val[gid] & 0xFF);
        g_pk[gid] = pk;
        int g1 = r >> 6;
        if (gid == 0) {
            for (int g = 0; g <= g1; g++) g_grp[g] = 0;
        } else {
            int g0 = rows[gid - 1] >> 6;
            for (int g = g0 + 1; g <= g1; g++) g_grp[g] = gid;
        }
        if (gid == nnz - 1) {
            for (int g = g1 + 1; g <= 64; g++) g_grp[g] = nnz;
        }
    }

    if (gid < (BATCH * M_IN) / 4) {
        const int idx = gid * 4;
        float4 v = *reinterpret_cast<const float4*>(x + idx);
        __half2* xp = reinterpret_cast<__half2*>(g_xh + idx);
        xp[0] = __floats2half2_rn(v.x, v.y);
        xp[1] = __floats2half2_rn(v.z, v.w);
        *reinterpret_cast<float4*>(out + idx) =
            *reinterpret_cast<const float4*>(bias + (idx & (N_OUT - 1)));
    }
}

// ---------------------------------------------------------------------------
// K1: fused build-B-in-smem + GEMM.
// CTA: 64 output rows (blockIdx.x), K slice of 1024 (blockIdx.y). 256 threads.
// B[64][1024] fp16 resident in smem as 16 k-tiles of [64 rows][64 cols],
// row stride 128B, 16B chunk c of row r stored at chunk (c ^ (r&7)).
// A (x fp16) streamed via 4-stage cp.async, 128x64 per k-tile.
// 8 warps as 4(m) x 2(n), warp tile 32x32 of m16n8k16.
// ---------------------------------------------------------------------------
__global__ void __launch_bounds__(256, 1)
k_gemm(const float* __restrict__ scales, float* __restrict__ out) {
    extern __shared__ __align__(1024) char smc[];
    __half* sm = reinterpret_cast<__half*>(smc);

    const int tid  = threadIdx.x;
    const int lane = tid & 31;
    const int warp = tid >> 5;
    const int wm   = warp & 3;       // 32-row M strip
    const int wn   = warp >> 2;      // 32-col N strip
    const int bn0  = blockIdx.x * BN;
    const int kbase = blockIdx.y * KPER;

    // ---- zero B region (128KB): 32 uint4 per thread ----
    {
        uint4* bz = reinterpret_cast<uint4*>(smc);
        uint4 z; z.x = 0; z.y = 0; z.z = 0; z.w = 0;
#pragma unroll
        for (int i = 0; i < 32; i++) bz[tid + i * 256] = z;
    }

    // ---- A prologue loads (overlap with scatter) ----
    uint32_t aoff[4];
    const __half* asrc[4];
#pragma unroll
    for (int i = 0; i < 4; i++) {
        int q = tid + i * 256;           // 0..1023
        int r = q >> 3, c = q & 7;
        aoff[i] = SMEM_A_OFF + (r * 64 + ((c ^ (r & 7)) << 3)) * 2;
        asrc[i] = g_xh + r * M_IN + kbase + (c << 3);
    }
    const uint32_t smb = smem_u32(smc);
    auto load_stage = [&](int s, int kofs) {
        uint32_t sb = smb + s * ASTG_BYTES;
#pragma unroll
        for (int i = 0; i < 4; i++) cpasync16(sb + aoff[i], asrc[i] + kofs);
    };
#pragma unroll
    for (int s = 0; s < ASTAGES - 1; s++) {
        load_stage(s, s * BK);
        asm volatile("cp.async.commit_group;");
    }

    __syncthreads();   // B zero visible before scatter

    // ---- scatter this CTA's nnz segment into smem B ----
    {
        const int lo = g_grp[blockIdx.x];
        const int hi = g_grp[blockIdx.x + 1];
        for (int i = lo + tid; i < hi; i += 256) {
            uint32_t pk = g_pk[i];
            unsigned cc = ((pk >> 8) & 0xFFF) - (unsigned)kbase;
            if (cc < (unsigned)KPER) {
                int r6 = (pk >> 20) & 63;
                int v  = (int)(pk << 24) >> 24;
                int kt = cc >> 6, ci = cc & 63;
                uint32_t b = kt * 8192 + r6 * 128
                           + ((((ci >> 3) ^ (r6 & 7)) << 4)) + ((ci & 7) << 1);
                atomicAdd(reinterpret_cast<__half*>(smc + b),
                          __float2half_rn((float)v));
            }
        }
    }
    __syncthreads();   // B complete before MMA reads

    float acc[2][4][4];
#pragma unroll
    for (int i = 0; i < 2; i++)
#pragma unroll
        for (int j = 0; j < 4; j++)
#pragma unroll
            for (int q = 0; q < 4; q++) acc[i][j][q] = 0.0f;

#pragma unroll 1
    for (int kt = 0; kt < KT; ++kt) {
        asm volatile("cp.async.wait_group %0;" :: "n"(ASTAGES - 2));
        __syncthreads();

        if (kt + ASTAGES - 1 < KT)
            load_stage((kt + ASTAGES - 1) & (ASTAGES - 1), (kt + ASTAGES - 1) * BK);
        asm volatile("cp.async.commit_group;");

        const __half* As = sm + (SMEM_A_OFF / 2) + (kt & (ASTAGES - 1)) * (ASTG_BYTES / 2);
        const char*   Bb = smc + kt * 8192;

#pragma unroll
        for (int ks = 0; ks < 4; ++ks) {
            uint32_t af[2][4];
#pragma unroll
            for (int mi = 0; mi < 2; mi++) {
                int row = wm * 32 + mi * 16 + (lane & 7) + ((lane >> 3) & 1) * 8;
                int ch  = ks * 2 + (lane >> 4);
                ldsm4(af[mi], smem_u32(As + row * 64 + ((ch ^ (row & 7)) << 3)));
            }
#pragma unroll
            for (int ni = 0; ni < 4; ni++) {
                int rowb = wn * 32 + ni * 8 + (lane & 7);
                int chb  = ks * 2 + ((lane >> 3) & 1);
                uint32_t bf[2];
                ldsm2(bf, smem_u32(Bb + rowb * 128 + ((chb ^ (rowb & 7)) << 4)));
#pragma unroll
                for (int mi = 0; mi < 2; mi++)
                    mma16816(acc[mi][ni], af[mi], bf);
            }
        }
        __syncthreads();
    }

    // ---- epilogue: scale + atomic add into bias-initialized out ----
#pragma unroll
    for (int ni = 0; ni < 4; ni++) {
        int nq = bn0 + wn * 32 + ni * 8 + ((lane & 3) << 1);
        float s0 = __ldg(scales + nq);
        float s1 = __ldg(scales + nq + 1);
#pragma unroll
        for (int mi = 0; mi < 2; mi++) {
            int r0 = wm * 32 + mi * 16 + (lane >> 2);
            redv2(out + (size_t)r0 * N_OUT + nq,
                  acc[mi][ni][0] * s0, acc[mi][ni][1] * s1);
            redv2(out + (size_t)(r0 + 8) * N_OUT + nq,
                  acc[mi][ni][2] * s0, acc[mi][ni][3] * s1);
        }
    }
}

// ---------------------------------------------------------------------------
extern "C" void kernel_launch(void* const* d_in, const int* in_sizes, int n_in,
                              void* d_out, int out_size) {
    const float* x    = (const float*)d_in[0];
    const int*   wval = (const int*)d_in[1];
    const float* wsc  = (const float*)d_in[2];
    const int*   rows = (const int*)d_in[3];
    const int*   cols = (const int*)d_in[4];
    const float* bias = (const float*)d_in[5];
    float* out = (float*)d_out;
    const int nnz = in_sizes[1];

    cudaFuncSetAttribute(k_gemm, cudaFuncAttributeMaxDynamicSharedMemorySize, SMEM_BYTES);

    k_prep<<<(nnz + 255) / 256, 256>>>(x, bias, out, wval, rows, cols, nnz);
    k_gemm<<<dim3(N_OUT / BN, SPLITK), 256, SMEM_BYTES>>>(wsc, out);
}

// round 8
// speedup vs baseline: 1.7576x; 1.7576x over previous
#include <cuda_runtime.h>
#include <cuda_fp16.h>
#include <cstdint>

#define N_OUT 4096
#define M_IN  4096
#define BATCH 128
#define KTOT  4096
#define BN    128
#define SPLITK 4
#define KPER  (KTOT / SPLITK)   // 1024
#define BK    64
#define KT    (KPER / BK)       // 16
#define STAGES 5
// stage: A 128x64 fp16 (16KB) + B 128x64 fp16 (16KB) = 32KB
#define STG_BYTES 32768
#define SMEM_BYTES (STAGES * STG_BYTES)   // 163840

// Scratch (device globals; no allocation allowed)
__device__ __align__(16) __half g_Wh[(size_t)N_OUT * M_IN];   // 32MB dense fp16 W
__device__ __align__(16) __half g_xh[BATCH * M_IN];           // x in fp16

// ---------------------------------------------------------------------------
__device__ __forceinline__ uint32_t smem_u32(const void* p) {
    return (uint32_t)__cvta_generic_to_shared(p);
}
__device__ __forceinline__ void cpasync16(uint32_t dst, const void* src) {
    asm volatile("cp.async.cg.shared.global [%0], [%1], 16;" :: "r"(dst), "l"(src));
}
__device__ __forceinline__ void ldsm4(uint32_t* r, uint32_t a) {
    asm volatile("ldmatrix.sync.aligned.m8n8.x4.shared.b16 {%0,%1,%2,%3}, [%4];"
                 : "=r"(r[0]), "=r"(r[1]), "=r"(r[2]), "=r"(r[3]) : "r"(a));
}
__device__ __forceinline__ void ldsm2(uint32_t* r, uint32_t a) {
    asm volatile("ldmatrix.sync.aligned.m8n8.x2.shared.b16 {%0,%1}, [%2];"
                 : "=r"(r[0]), "=r"(r[1]) : "r"(a));
}
__device__ __forceinline__ void mma16816(float* c, const uint32_t* a, const uint32_t* b) {
    asm volatile(
        "mma.sync.aligned.m16n8k16.row.col.f32.f16.f16.f32 "
        "{%0,%1,%2,%3}, {%4,%5,%6,%7}, {%8,%9}, {%0,%1,%2,%3};"
        : "+f"(c[0]), "+f"(c[1]), "+f"(c[2]), "+f"(c[3])
        : "r"(a[0]), "r"(a[1]), "r"(a[2]), "r"(a[3]), "r"(b[0]), "r"(b[1]));
}
__device__ __forceinline__ void redv2(float* p, float x, float y) {
    asm volatile("red.global.add.v2.f32 [%0], {%1, %2};"
                 :: "l"(p), "f"(x), "f"(y) : "memory");
}

// ---------------------------------------------------------------------------
// K0 (fused): zero W, convert x -> fp16, init out with bias
// ---------------------------------------------------------------------------
__global__ void k_prep(const float* __restrict__ x,
                       const float* __restrict__ bias,
                       float* __restrict__ out) {
    const int gid = blockIdx.x * blockDim.x + threadIdx.x;
    const int nthr = gridDim.x * blockDim.x;

    uint4* wp = reinterpret_cast<uint4*>(g_Wh);
    uint4 z; z.x = 0; z.y = 0; z.z = 0; z.w = 0;
    const int n4 = (int)(((size_t)N_OUT * M_IN) / 8);
    for (int i = gid; i < n4; i += nthr) wp[i] = z;

    if (gid < (BATCH * M_IN) / 4) {
        const int idx = gid * 4;
        float4 v = *reinterpret_cast<const float4*>(x + idx);
        __half2* xp = reinterpret_cast<__half2*>(g_xh + idx);
        xp[0] = __floats2half2_rn(v.x, v.y);
        xp[1] = __floats2half2_rn(v.z, v.w);
        *reinterpret_cast<float4*>(out + idx) =
            *reinterpret_cast<const float4*>(bias + (idx & (N_OUT - 1)));
    }
}

// ---------------------------------------------------------------------------
// K1: scatter quantized values into dense fp16 W (duplicates accumulate)
// ---------------------------------------------------------------------------
__global__ void k_scatter(const int* __restrict__ val,
                          const int* __restrict__ rows,
                          const int* __restrict__ cols,
                          int nnz4) {
    int i = blockIdx.x * blockDim.x + threadIdx.x;
    if (i < nnz4) {
        int4 v = reinterpret_cast<const int4*>(val)[i];
        int4 r = reinterpret_cast<const int4*>(rows)[i];
        int4 c = reinterpret_cast<const int4*>(cols)[i];
        atomicAdd(&g_Wh[(size_t)r.x * M_IN + c.x], __float2half_rn((float)v.x));
        atomicAdd(&g_Wh[(size_t)r.y * M_IN + c.y], __float2half_rn((float)v.y));
        atomicAdd(&g_Wh[(size_t)r.z * M_IN + c.z], __float2half_rn((float)v.z));
        atomicAdd(&g_Wh[(size_t)r.w * M_IN + c.w], __float2half_rn((float)v.w));
    }
}

// ---------------------------------------------------------------------------
// K2: GEMM  out[b,n] += scale[n] * sum_k x_h[b,k] * W[n,k]
// CTA tile 128(batch) x 128(N), BK=64, 5-stage cp.async, split-K=4.
// 8 warps as 2(m) x 4(n); warp tile 64x32 (mi<4 x ni<4 of m16n8k16).
// smem stage: A[128][64] @ +0, B[128][64] @ +16KB; rows of 64 halves,
// 16B chunk c of row r stored at chunk (c ^ (r&7)).
// ---------------------------------------------------------------------------
__global__ void __launch_bounds__(256, 1)
k_gemm(const float* __restrict__ scales, float* __restrict__ out) {
    extern __shared__ __align__(1024) char smc[];

    const int tid  = threadIdx.x;
    const int lane = tid & 31;
    const int warp = tid >> 5;
    const int wm   = warp & 1;       // 0..1 -> 64-row M strip
    const int wn   = warp >> 1;      // 0..3 -> 32-col N strip
    const int bn0  = blockIdx.x * BN;
    const int kbase = blockIdx.y * KPER;

    float acc[4][4][4];
#pragma unroll
    for (int i = 0; i < 4; i++)
#pragma unroll
        for (int j = 0; j < 4; j++)
#pragma unroll
            for (int q = 0; q < 4; q++) acc[i][j][q] = 0.0f;

    // per-thread load coords: 4 A chunks + 4 B chunks of 16B each
    uint32_t aoff[4], boff[4];
    const __half* asrc[4];
    const __half* bsrc[4];
#pragma unroll
    for (int i = 0; i < 4; i++) {
        int q = tid + i * 256;           // 0..1023
        int r = q >> 3, c = q & 7;
        uint32_t sw = (r * 64 + ((c ^ (r & 7)) << 3)) * 2;
        aoff[i] = sw;
        boff[i] = 16384 + sw;
        asrc[i] = g_xh + r * M_IN + kbase + (c << 3);
        bsrc[i] = g_Wh + (size_t)(bn0 + r) * M_IN + kbase + (c << 3);
    }

    const uint32_t smb = smem_u32(smc);

    auto load_stage = [&](int s, int kofs) {
        uint32_t sb = smb + s * STG_BYTES;
#pragma unroll
        for (int i = 0; i < 4; i++) cpasync16(sb + aoff[i], asrc[i] + kofs);
#pragma unroll
        for (int i = 0; i < 4; i++) cpasync16(sb + boff[i], bsrc[i] + kofs);
    };

    // prologue: stages 0..3
#pragma unroll
    for (int s = 0; s < STAGES - 1; s++) {
        load_stage(s, s * BK);
        asm volatile("cp.async.commit_group;");
    }

    int slot = 0;                         // consume slot = kt % 5
    int wslot = STAGES - 1;               // write slot = (kt+4) % 5

#pragma unroll 1
    for (int kt = 0; kt < KT; ++kt) {
        asm volatile("cp.async.wait_group %0;" :: "n"(STAGES - 2));
        __syncthreads();

        if (kt + STAGES - 1 < KT)
            load_stage(wslot, (kt + STAGES - 1) * BK);
        asm volatile("cp.async.commit_group;");
        if (++wslot == STAGES) wslot = 0;

        const char* As = smc + slot * STG_BYTES;
        const char* Bs = As + 16384;
        if (++slot == STAGES) slot = 0;

#pragma unroll
        for (int ks = 0; ks < 4; ++ks) {
            uint32_t af[4][4];
#pragma unroll
            for (int mi = 0; mi < 4; mi++) {
                int row = wm * 64 + mi * 16 + (lane & 7) + ((lane >> 3) & 1) * 8;
                int ch  = ks * 2 + (lane >> 4);
                ldsm4(af[mi], smem_u32(As + (row * 64 + ((ch ^ (row & 7)) << 3)) * 2));
            }
#pragma unroll
            for (int ni = 0; ni < 4; ni++) {
                int rowb = wn * 32 + ni * 8 + (lane & 7);
                int chb  = ks * 2 + ((lane >> 3) & 1);
                uint32_t bf[2];
                ldsm2(bf, smem_u32(Bs + (rowb * 64 + ((chb ^ (rowb & 7)) << 3)) * 2));
#pragma unroll
                for (int mi = 0; mi < 4; mi++)
                    mma16816(acc[mi][ni], af[mi], bf);
            }
        }
    }

    // epilogue: scale + atomic add into bias-initialized out
#pragma unroll
    for (int ni = 0; ni < 4; ni++) {
        int nq = bn0 + wn * 32 + ni * 8 + ((lane & 3) << 1);
        float s0 = __ldg(scales + nq);
        float s1 = __ldg(scales + nq + 1);
#pragma unroll
        for (int mi = 0; mi < 4; mi++) {
            int r0 = wm * 64 + mi * 16 + (lane >> 2);
            redv2(out + (size_t)r0 * N_OUT + nq,
                  acc[mi][ni][0] * s0, acc[mi][ni][1] * s1);
            redv2(out + (size_t)(r0 + 8) * N_OUT + nq,
                  acc[mi][ni][2] * s0, acc[mi][ni][3] * s1);
        }
    }
}

// ---------------------------------------------------------------------------
extern "C" void kernel_launch(void* const* d_in, const int* in_sizes, int n_in,
                              void* d_out, int out_size) {
    const float* x    = (const float*)d_in[0];
    const int*   wval = (const int*)d_in[1];
    const float* wsc  = (const float*)d_in[2];
    const int*   rows = (const int*)d_in[3];
    const int*   cols = (const int*)d_in[4];
    const float* bias = (const float*)d_in[5];
    float* out = (float*)d_out;
    const int nnz = in_sizes[1];
    const int nnz4 = nnz / 4;

    cudaFuncSetAttribute(k_gemm, cudaFuncAttributeMaxDynamicSharedMemorySize, SMEM_BYTES);

    k_prep<<<4096, 256>>>(x, bias, out);
    k_scatter<<<(nnz4 + 255) / 256, 256>>>(wval, rows, cols, nnz4);
    k_gemm<<<dim3(N_OUT / BN, SPLITK), 256, SMEM_BYTES>>>(wsc, out);
}